// round 5
// baseline (speedup 1.0000x reference)
#include <cuda_runtime.h>

#define DM 1024
#define NH 16
#define HD 64
#define BB 2
#define TT 2048
#define MM (BB*TT)   // 4096 rows

// Scratch (no cudaMalloc allowed): Q, K, V in [B,H,T,D], attn out in [B,T,H*D]
__device__ float g_q[(size_t)MM * DM];
__device__ float g_k[(size_t)MM * DM];
__device__ float g_v[(size_t)MM * DM];
__device__ float g_attn[(size_t)MM * DM];

// ---------------------------------------------------------------------------
// SGEMM: C = A @ B^T   (A: [M,K] row-major, B: [N,K] row-major)
// M=4096, N=1024, K=1024.  BM=BN=128, BK=8, 8x8 per thread, 256 threads.
// MODE 0: C row-major [M,N].  MODE 1: write in [B,H,T,D] permuted layout.
// ---------------------------------------------------------------------------
template<int MODE>
__global__ __launch_bounds__(256)
void sgemm_abt(const float* __restrict__ A, const float* __restrict__ Bm,
               float* __restrict__ C)
{
    const int K = DM, N = DM;
    __shared__ float As[8 * 128];
    __shared__ float Bs[8 * 128];

    const int tid  = threadIdx.x;
    const int brow = blockIdx.y;
    const int bcol = blockIdx.x;

    const int rowA = tid >> 1;          // 0..127
    const int colA = (tid & 1) << 2;    // 0 or 4
    const int tr   = tid >> 4;          // 0..15
    const int tc   = tid & 15;          // 0..15

    const float* Aptr = A  + (size_t)(brow * 128 + rowA) * K + colA;
    const float* Bptr = Bm + (size_t)(bcol * 128 + rowA) * K + colA;

    float acc[8][8];
    #pragma unroll
    for (int i = 0; i < 8; i++)
        #pragma unroll
        for (int j = 0; j < 8; j++) acc[i][j] = 0.f;

    for (int kt = 0; kt < K; kt += 8) {
        float4 av = *(const float4*)(Aptr + kt);
        float4 bv = *(const float4*)(Bptr + kt);
        As[(colA + 0) * 128 + rowA] = av.x;
        As[(colA + 1) * 128 + rowA] = av.y;
        As[(colA + 2) * 128 + rowA] = av.z;
        As[(colA + 3) * 128 + rowA] = av.w;
        Bs[(colA + 0) * 128 + rowA] = bv.x;
        Bs[(colA + 1) * 128 + rowA] = bv.y;
        Bs[(colA + 2) * 128 + rowA] = bv.z;
        Bs[(colA + 3) * 128 + rowA] = bv.w;
        __syncthreads();

        #pragma unroll
        for (int k = 0; k < 8; k++) {
            float4 a0 = *(const float4*)(As + k * 128 + tr * 8);
            float4 a1 = *(const float4*)(As + k * 128 + tr * 8 + 4);
            float4 b0 = *(const float4*)(Bs + k * 128 + tc * 8);
            float4 b1 = *(const float4*)(Bs + k * 128 + tc * 8 + 4);
            float ra[8] = {a0.x, a0.y, a0.z, a0.w, a1.x, a1.y, a1.z, a1.w};
            float rb[8] = {b0.x, b0.y, b0.z, b0.w, b1.x, b1.y, b1.z, b1.w};
            #pragma unroll
            for (int i = 0; i < 8; i++)
                #pragma unroll
                for (int j = 0; j < 8; j++)
                    acc[i][j] += ra[i] * rb[j];
        }
        __syncthreads();
    }

    const int crow0 = brow * 128 + tr * 8;
    const int ccol0 = bcol * 128 + tc * 8;
    if (MODE == 0) {
        #pragma unroll
        for (int i = 0; i < 8; i++) {
            float4 v0 = make_float4(acc[i][0], acc[i][1], acc[i][2], acc[i][3]);
            float4 v1 = make_float4(acc[i][4], acc[i][5], acc[i][6], acc[i][7]);
            *(float4*)(C + (size_t)(crow0 + i) * N + ccol0)     = v0;
            *(float4*)(C + (size_t)(crow0 + i) * N + ccol0 + 4) = v1;
        }
    } else {
        // permute: m = b*T + t, n = h*64 + d  ->  ((b*16+h)*2048 + t)*64 + d
        #pragma unroll
        for (int i = 0; i < 8; i++) {
            int m = crow0 + i;
            int b = m >> 11, t = m & 2047;
            #pragma unroll
            for (int j = 0; j < 8; j++) {
                int n = ccol0 + j;
                int h = n >> 6, d = n & 63;
                C[((size_t)((b << 4) + h) * TT + t) * HD + d] = acc[i][j];
            }
        }
    }
}

// ---------------------------------------------------------------------------
// Flash attention fp32.  One CTA per (b, h, 64-row q block).
// BR=BC=64, 256 threads (16x16), 4x4 regs for S and O per thread.
// Q and K kept transposed [d][t]/[d][s] in smem with XOR-4 swizzle.
// P (softmax probs) reuses K's buffer. Static smem = exactly 48KB.
// ---------------------------------------------------------------------------
__device__ __forceinline__ int swz4(int d) { return ((d >> 2) & 15) << 2; }

__global__ __launch_bounds__(256)
void flash_attn(const float* __restrict__ gq, const float* __restrict__ gk,
                const float* __restrict__ gv, float* __restrict__ gout)
{
    __shared__ float Qs [64 * 64];   // [d][t^swz]
    __shared__ float KPs[64 * 64];   // K: [d][s^swz], later P: [t][s]
    __shared__ float Vs [64 * 64];   // [s][d]

    const int qb  = blockIdx.x;   // 0..31
    const int h   = blockIdx.y;
    const int b   = blockIdx.z;
    const int tid = threadIdx.x;
    const int ty  = tid >> 4;     // 0..15 -> rows ty*4..+3
    const int tx  = tid & 15;     // 0..15 -> cols tx*4..+3

    const size_t bh   = (size_t)(b * NH + h) * TT;
    const float* qptr = gq + (bh + (size_t)qb * 64) * HD;
    const float  qscale = 0.125f;   // 1/sqrt(64)

    // load Q transposed + swizzled, pre-scaled
    #pragma unroll
    for (int it = 0; it < 4; it++) {
        int lin = (tid + it * 256) * 4;
        int t = lin >> 6, d0 = lin & 63;
        float4 v = *(const float4*)(qptr + lin);
        int ts = t ^ swz4(d0);
        Qs[(d0 + 0) * 64 + ts] = v.x * qscale;
        Qs[(d0 + 1) * 64 + ts] = v.y * qscale;
        Qs[(d0 + 2) * 64 + ts] = v.z * qscale;
        Qs[(d0 + 3) * 64 + ts] = v.w * qscale;
    }

    float m_i[4], l_i[4], o[4][4];
    #pragma unroll
    for (int i = 0; i < 4; i++) {
        m_i[i] = -1e30f; l_i[i] = 0.f;
        #pragma unroll
        for (int j = 0; j < 4; j++) o[i][j] = 0.f;
    }

    for (int jb = 0; jb <= qb; jb++) {
        const float* kptr = gk + (bh + (size_t)jb * 64) * HD;
        const float* vptr = gv + (bh + (size_t)jb * 64) * HD;
        __syncthreads();   // previous iteration done with smem (also fences Q load)
        #pragma unroll
        for (int it = 0; it < 4; it++) {
            int lin = (tid + it * 256) * 4;
            int s = lin >> 6, d0 = lin & 63;
            float4 kv = *(const float4*)(kptr + lin);
            int ss = s ^ swz4(d0);
            KPs[(d0 + 0) * 64 + ss] = kv.x;
            KPs[(d0 + 1) * 64 + ss] = kv.y;
            KPs[(d0 + 2) * 64 + ss] = kv.z;
            KPs[(d0 + 3) * 64 + ss] = kv.w;
            *(float4*)(Vs + lin) = *(const float4*)(vptr + lin);
        }
        __syncthreads();

        // S = Q @ K^T  (pre-scaled)
        float acc[4][4];
        #pragma unroll
        for (int i = 0; i < 4; i++)
            #pragma unroll
            for (int j = 0; j < 4; j++) acc[i][j] = 0.f;

        #pragma unroll
        for (int d = 0; d < 64; d++) {
            int sw = swz4(d);
            float4 qv = *(const float4*)(Qs  + d * 64 + ((ty * 4) ^ sw));
            float4 kv = *(const float4*)(KPs + d * 64 + ((tx * 4) ^ sw));
            float qa[4] = {qv.x, qv.y, qv.z, qv.w};
            float ka[4] = {kv.x, kv.y, kv.z, kv.w};
            #pragma unroll
            for (int i = 0; i < 4; i++)
                #pragma unroll
                for (int j = 0; j < 4; j++)
                    acc[i][j] += qa[i] * ka[j];
        }

        // causal mask (only the diagonal block)
        if (jb == qb) {
            #pragma unroll
            for (int i = 0; i < 4; i++)
                #pragma unroll
                for (int j = 0; j < 4; j++)
                    if (tx * 4 + j > ty * 4 + i) acc[i][j] = -1e30f;
        }

        // online softmax (per-row over 16 tx lanes)
        #pragma unroll
        for (int i = 0; i < 4; i++) {
            float mx = fmaxf(fmaxf(acc[i][0], acc[i][1]),
                             fmaxf(acc[i][2], acc[i][3]));
            #pragma unroll
            for (int off = 8; off > 0; off >>= 1)
                mx = fmaxf(mx, __shfl_xor_sync(0xffffffffu, mx, off, 16));
            float mnew  = fmaxf(m_i[i], mx);
            float alpha = __expf(m_i[i] - mnew);
            m_i[i] = mnew;
            float rs = 0.f;
            #pragma unroll
            for (int j = 0; j < 4; j++) {
                acc[i][j] = __expf(acc[i][j] - mnew);
                rs += acc[i][j];
            }
            #pragma unroll
            for (int off = 8; off > 0; off >>= 1)
                rs += __shfl_xor_sync(0xffffffffu, rs, off, 16);
            l_i[i] = l_i[i] * alpha + rs;
            #pragma unroll
            for (int j = 0; j < 4; j++) o[i][j] *= alpha;
        }

        __syncthreads();   // all threads done reading K from KPs
        // write P into KPs, row-major [t][s]
        #pragma unroll
        for (int i = 0; i < 4; i++)
            *(float4*)(KPs + (ty * 4 + i) * 64 + tx * 4) =
                make_float4(acc[i][0], acc[i][1], acc[i][2], acc[i][3]);
        __syncthreads();

        // O += P @ V
        #pragma unroll
        for (int s = 0; s < 64; s++) {
            float4 vv = *(const float4*)(Vs + s * 64 + tx * 4);
            #pragma unroll
            for (int i = 0; i < 4; i++) {
                float p = KPs[(ty * 4 + i) * 64 + s];
                o[i][0] += p * vv.x;
                o[i][1] += p * vv.y;
                o[i][2] += p * vv.z;
                o[i][3] += p * vv.w;
            }
        }
    }

    // epilogue: O /= l, write [B,T,H*D]
    #pragma unroll
    for (int i = 0; i < 4; i++) {
        float inv = 1.f / l_i[i];
        int t = qb * 64 + ty * 4 + i;
        float4 ov = make_float4(o[i][0] * inv, o[i][1] * inv,
                                o[i][2] * inv, o[i][3] * inv);
        *(float4*)(gout + (size_t)(b * TT + t) * DM + h * HD + tx * 4) = ov;
    }
}

// ---------------------------------------------------------------------------
extern "C" void kernel_launch(void* const* d_in, const int* in_sizes, int n_in,
                              void* d_out, int out_size)
{
    const float* x  = (const float*)d_in[0];
    const float* Wq = (const float*)d_in[1];
    const float* Wk = (const float*)d_in[2];
    const float* Wv = (const float*)d_in[3];
    const float* Wo = (const float*)d_in[4];
    float* out = (float*)d_out;

    float *gq, *gk, *gv, *ga;
    cudaGetSymbolAddress((void**)&gq, g_q);
    cudaGetSymbolAddress((void**)&gk, g_k);
    cudaGetSymbolAddress((void**)&gv, g_v);
    cudaGetSymbolAddress((void**)&ga, g_attn);

    dim3 gemm_grid(DM / 128, MM / 128);   // (8, 32)
    sgemm_abt<1><<<gemm_grid, 256>>>(x, Wq, gq);
    sgemm_abt<1><<<gemm_grid, 256>>>(x, Wk, gk);
    sgemm_abt<1><<<gemm_grid, 256>>>(x, Wv, gv);

    flash_attn<<<dim3(TT / 64, NH, BB), 256>>>(gq, gk, gv, ga);

    sgemm_abt<0><<<gemm_grid, 256>>>(ga, Wo, out);
}

// round 7
// speedup vs baseline: 1.6134x; 1.6134x over previous
#include <cuda_runtime.h>
#include <cuda_bf16.h>
#include <cstdint>

#define DM 1024
#define NH 16
#define HD 64
#define BB 2
#define TT 2048
#define MM (BB*TT)   // 4096 rows

// Scratch: Q, K, V in [B,H,T,D], attn out in [B,T,H*D]
__device__ float g_q[(size_t)MM * DM];
__device__ float g_k[(size_t)MM * DM];
__device__ float g_v[(size_t)MM * DM];
__device__ float g_attn[(size_t)MM * DM];

__device__ __forceinline__ uint32_t smem_addr_u32(const void* smem_ptr) {
    uint32_t addr;
    asm("{ .reg .u64 tmp; cvta.to.shared.u64 tmp, %1; cvt.u32.u64 %0, tmp; }"
        : "=r"(addr) : "l"(smem_ptr));
    return addr;
}

#define SMEM_SWIZZLE_128B(byte_offset) \
    ((byte_offset) ^ (((byte_offset) >> 3) & 0x70))

__device__ __forceinline__ void ldmatrix_x4(uint32_t& r0, uint32_t& r1,
                                            uint32_t& r2, uint32_t& r3,
                                            uint32_t addr) {
    asm volatile("ldmatrix.sync.aligned.m8n8.x4.shared.b16 {%0,%1,%2,%3}, [%4];"
                 : "=r"(r0), "=r"(r1), "=r"(r2), "=r"(r3) : "r"(addr));
}

__device__ __forceinline__ void mma_bf16(float* d, const uint32_t* a,
                                         uint32_t b0, uint32_t b1) {
    asm volatile(
        "mma.sync.aligned.m16n8k16.row.col.f32.bf16.bf16.f32 "
        "{%0,%1,%2,%3}, {%4,%5,%6,%7}, {%8,%9}, {%0,%1,%2,%3};"
        : "+f"(d[0]), "+f"(d[1]), "+f"(d[2]), "+f"(d[3])
        : "r"(a[0]), "r"(a[1]), "r"(a[2]), "r"(a[3]), "r"(b0), "r"(b1));
}

__device__ __forceinline__ uint32_t pack_bf2(__nv_bfloat16 a, __nv_bfloat16 b) {
    return ((uint32_t)__bfloat16_as_ushort(b) << 16) | (uint32_t)__bfloat16_as_ushort(a);
}

__device__ __forceinline__ void split_store(char* phi, char* plo, uint32_t off,
                                            float4 v) {
    __nv_bfloat16 h0 = __float2bfloat16_rn(v.x);
    __nv_bfloat16 h1 = __float2bfloat16_rn(v.y);
    __nv_bfloat16 h2 = __float2bfloat16_rn(v.z);
    __nv_bfloat16 h3 = __float2bfloat16_rn(v.w);
    __nv_bfloat16 l0 = __float2bfloat16_rn(v.x - __bfloat162float(h0));
    __nv_bfloat16 l1 = __float2bfloat16_rn(v.y - __bfloat162float(h1));
    __nv_bfloat16 l2 = __float2bfloat16_rn(v.z - __bfloat162float(h2));
    __nv_bfloat16 l3 = __float2bfloat16_rn(v.w - __bfloat162float(h3));
    *(uint2*)(phi + off) = make_uint2(pack_bf2(h0, h1), pack_bf2(h2, h3));
    *(uint2*)(plo + off) = make_uint2(pack_bf2(l0, l1), pack_bf2(l2, l3));
}

// ===========================================================================
// Warp-MMA GEMM: C = A @ B^T.  A:[4096,1024], B:[1024,1024] fp32 row-major.
// CTA tile 128x128, K staged in chunks of 64, bf16 hi/lo split (3 mmas).
// 8 warps (4x2), warp tile 32x64.  Smem/stage: Ahi,Alo,Bhi,Blo 16KB = 64KB.
// MODE 0: C row-major.  MODE 1: C in [B,H,T,D] permuted layout.
// ===========================================================================
#define GEMM_SMEM 65536

template<int MODE>
__global__ __launch_bounds__(256, 2)
void gemm_mma(const float* __restrict__ A, const float* __restrict__ Bm,
              float* __restrict__ C)
{
    extern __shared__ __align__(1024) char smem[];
    char* sAh = smem;
    char* sAl = smem + 16384;
    char* sBh = smem + 32768;
    char* sBl = smem + 49152;
    const uint32_t uAh = smem_addr_u32(sAh);
    const uint32_t uAl = uAh + 16384;
    const uint32_t uBh = uAh + 32768;
    const uint32_t uBl = uAh + 49152;

    const int tid  = threadIdx.x;
    const int bcol = blockIdx.x;
    const int brow = blockIdx.y;
    const int warp = tid >> 5;
    const int lane = tid & 31;

    const int m0w = (warp >> 1) * 32;   // warp M offset in tile
    const int n0w = (warp & 1) * 64;    // warp N offset in tile

    // ldmatrix lane address components (shared by A and B):
    // row = rbase + (tile&1)*8 + within ; chunk-half = (tile>>1)*16
    const int ltile   = lane >> 3;
    const int within  = lane & 7;
    const int rowoff  = ((ltile & 1) << 3) + within;   // 0..15
    const int chalf   = (ltile >> 1) << 4;             // 0 or 16
    const int xorkey  = within << 4;

    const float* Ag = A  + (size_t)(brow * 128) * DM;
    const float* Bg = Bm + (size_t)(bcol * 128) * DM;

    float acc[2][8][4];
    #pragma unroll
    for (int i = 0; i < 2; i++)
        #pragma unroll
        for (int j = 0; j < 8; j++)
            #pragma unroll
            for (int q = 0; q < 4; q++) acc[i][j][q] = 0.f;

    for (int s = 0; s < 16; ++s) {
        // ---- load + convert stage s ----
        #pragma unroll
        for (int it = 0; it < 8; ++it) {
            int idx = tid + it * 256;        // 0..2047 (float4 units)
            int r   = idx >> 4;              // 0..127
            int c4  = (idx & 15) << 2;       // 0..60
            float4 va = *(const float4*)(Ag + (size_t)r * DM + s * 64 + c4);
            float4 vb = *(const float4*)(Bg + (size_t)r * DM + s * 64 + c4);
            uint32_t off = SMEM_SWIZZLE_128B((uint32_t)(r * 128 + c4 * 2));
            split_store(sAh, sAl, off, va);
            split_store(sBh, sBl, off, vb);
        }
        __syncthreads();

        // ---- compute: 4 k16 steps ----
        #pragma unroll
        for (int ks = 0; ks < 4; ++ks) {
            const uint32_t coff = (uint32_t)((ks * 32 + chalf) ^ xorkey);

            uint32_t ah[2][4], al[2][4];
            #pragma unroll
            for (int i = 0; i < 2; i++) {
                uint32_t ra = (uint32_t)((m0w + i * 16 + rowoff) * 128) + coff;
                ldmatrix_x4(ah[i][0], ah[i][1], ah[i][2], ah[i][3], uAh + ra);
                ldmatrix_x4(al[i][0], al[i][1], al[i][2], al[i][3], uAl + ra);
            }

            #pragma unroll
            for (int g = 0; g < 4; ++g) {
                uint32_t rb = (uint32_t)((n0w + g * 16 + rowoff) * 128) + coff;
                uint32_t bh[4], bl[4];
                ldmatrix_x4(bh[0], bh[1], bh[2], bh[3], uBh + rb);
                ldmatrix_x4(bl[0], bl[1], bl[2], bl[3], uBl + rb);
                #pragma unroll
                for (int jj = 0; jj < 2; ++jj) {
                    int j = g * 2 + jj;
                    #pragma unroll
                    for (int i = 0; i < 2; i++) {
                        mma_bf16(acc[i][j], ah[i], bh[jj], bh[2 + jj]);
                        mma_bf16(acc[i][j], ah[i], bl[jj], bl[2 + jj]);
                        mma_bf16(acc[i][j], al[i], bh[jj], bh[2 + jj]);
                    }
                }
            }
        }
        __syncthreads();
    }

    // ---- epilogue ----
    const int rfrag = lane >> 2;          // 0..7
    const int cfrag = (lane & 3) * 2;     // 0,2,4,6
    #pragma unroll
    for (int i = 0; i < 2; i++) {
        #pragma unroll
        for (int j = 0; j < 8; j++) {
            int m = brow * 128 + m0w + i * 16 + rfrag;
            int n = bcol * 128 + n0w + j * 8 + cfrag;
            float2 v0 = make_float2(acc[i][j][0], acc[i][j][1]);
            float2 v1 = make_float2(acc[i][j][2], acc[i][j][3]);
            if (MODE == 0) {
                *(float2*)(C + (size_t)m * DM + n)       = v0;
                *(float2*)(C + (size_t)(m + 8) * DM + n) = v1;
            } else {
                int h = n >> 6, d = n & 63;
                int b0 = m >> 11, t0 = m & 2047;
                *(float2*)(C + ((size_t)((b0 << 4) + h) * TT + t0) * HD + d) = v0;
                int m8 = m + 8;
                int b1 = m8 >> 11, t1 = m8 & 2047;
                *(float2*)(C + ((size_t)((b1 << 4) + h) * TT + t1) * HD + d) = v1;
            }
        }
    }
}

// ---------------------------------------------------------------------------
// Flash attention fp32 (unchanged — 569us; tensorize next round).
// ---------------------------------------------------------------------------
__device__ __forceinline__ int swz4(int d) { return ((d >> 2) & 15) << 2; }

__global__ __launch_bounds__(256)
void flash_attn(const float* __restrict__ gq, const float* __restrict__ gk,
                const float* __restrict__ gv, float* __restrict__ gout)
{
    __shared__ float Qs [64 * 64];
    __shared__ float KPs[64 * 64];
    __shared__ float Vs [64 * 64];

    const int qb  = blockIdx.x;
    const int h   = blockIdx.y;
    const int b   = blockIdx.z;
    const int tid = threadIdx.x;
    const int ty  = tid >> 4;
    const int tx  = tid & 15;

    const size_t bh   = (size_t)(b * NH + h) * TT;
    const float* qptr = gq + (bh + (size_t)qb * 64) * HD;
    const float  qscale = 0.125f;

    #pragma unroll
    for (int it = 0; it < 4; it++) {
        int lin = (tid + it * 256) * 4;
        int t = lin >> 6, d0 = lin & 63;
        float4 v = *(const float4*)(qptr + lin);
        int ts = t ^ swz4(d0);
        Qs[(d0 + 0) * 64 + ts] = v.x * qscale;
        Qs[(d0 + 1) * 64 + ts] = v.y * qscale;
        Qs[(d0 + 2) * 64 + ts] = v.z * qscale;
        Qs[(d0 + 3) * 64 + ts] = v.w * qscale;
    }

    float m_i[4], l_i[4], o[4][4];
    #pragma unroll
    for (int i = 0; i < 4; i++) {
        m_i[i] = -1e30f; l_i[i] = 0.f;
        #pragma unroll
        for (int j = 0; j < 4; j++) o[i][j] = 0.f;
    }

    for (int jb = 0; jb <= qb; jb++) {
        const float* kptr = gk + (bh + (size_t)jb * 64) * HD;
        const float* vptr = gv + (bh + (size_t)jb * 64) * HD;
        __syncthreads();
        #pragma unroll
        for (int it = 0; it < 4; it++) {
            int lin = (tid + it * 256) * 4;
            int s = lin >> 6, d0 = lin & 63;
            float4 kv = *(const float4*)(kptr + lin);
            int ss = s ^ swz4(d0);
            KPs[(d0 + 0) * 64 + ss] = kv.x;
            KPs[(d0 + 1) * 64 + ss] = kv.y;
            KPs[(d0 + 2) * 64 + ss] = kv.z;
            KPs[(d0 + 3) * 64 + ss] = kv.w;
            *(float4*)(Vs + lin) = *(const float4*)(vptr + lin);
        }
        __syncthreads();

        float acc[4][4];
        #pragma unroll
        for (int i = 0; i < 4; i++)
            #pragma unroll
            for (int j = 0; j < 4; j++) acc[i][j] = 0.f;

        #pragma unroll
        for (int d = 0; d < 64; d++) {
            int sw = swz4(d);
            float4 qv = *(const float4*)(Qs  + d * 64 + ((ty * 4) ^ sw));
            float4 kv = *(const float4*)(KPs + d * 64 + ((tx * 4) ^ sw));
            float qa[4] = {qv.x, qv.y, qv.z, qv.w};
            float ka[4] = {kv.x, kv.y, kv.z, kv.w};
            #pragma unroll
            for (int i = 0; i < 4; i++)
                #pragma unroll
                for (int j = 0; j < 4; j++)
                    acc[i][j] += qa[i] * ka[j];
        }

        if (jb == qb) {
            #pragma unroll
            for (int i = 0; i < 4; i++)
                #pragma unroll
                for (int j = 0; j < 4; j++)
                    if (tx * 4 + j > ty * 4 + i) acc[i][j] = -1e30f;
        }

        #pragma unroll
        for (int i = 0; i < 4; i++) {
            float mx = fmaxf(fmaxf(acc[i][0], acc[i][1]),
                             fmaxf(acc[i][2], acc[i][3]));
            #pragma unroll
            for (int off = 8; off > 0; off >>= 1)
                mx = fmaxf(mx, __shfl_xor_sync(0xffffffffu, mx, off, 16));
            float mnew  = fmaxf(m_i[i], mx);
            float alpha = __expf(m_i[i] - mnew);
            m_i[i] = mnew;
            float rs = 0.f;
            #pragma unroll
            for (int j = 0; j < 4; j++) {
                acc[i][j] = __expf(acc[i][j] - mnew);
                rs += acc[i][j];
            }
            #pragma unroll
            for (int off = 8; off > 0; off >>= 1)
                rs += __shfl_xor_sync(0xffffffffu, rs, off, 16);
            l_i[i] = l_i[i] * alpha + rs;
            #pragma unroll
            for (int j = 0; j < 4; j++) o[i][j] *= alpha;
        }

        __syncthreads();
        #pragma unroll
        for (int i = 0; i < 4; i++)
            *(float4*)(KPs + (ty * 4 + i) * 64 + tx * 4) =
                make_float4(acc[i][0], acc[i][1], acc[i][2], acc[i][3]);
        __syncthreads();

        #pragma unroll
        for (int s = 0; s < 64; s++) {
            float4 vv = *(const float4*)(Vs + s * 64 + tx * 4);
            #pragma unroll
            for (int i = 0; i < 4; i++) {
                float p = KPs[(ty * 4 + i) * 64 + s];
                o[i][0] += p * vv.x;
                o[i][1] += p * vv.y;
                o[i][2] += p * vv.z;
                o[i][3] += p * vv.w;
            }
        }
    }

    #pragma unroll
    for (int i = 0; i < 4; i++) {
        float inv = 1.f / l_i[i];
        int t = qb * 64 + ty * 4 + i;
        float4 ov = make_float4(o[i][0] * inv, o[i][1] * inv,
                                o[i][2] * inv, o[i][3] * inv);
        *(float4*)(gout + (size_t)(b * TT + t) * DM + h * HD + tx * 4) = ov;
    }
}

// ---------------------------------------------------------------------------
extern "C" void kernel_launch(void* const* d_in, const int* in_sizes, int n_in,
                              void* d_out, int out_size)
{
    const float* x  = (const float*)d_in[0];
    const float* Wq = (const float*)d_in[1];
    const float* Wk = (const float*)d_in[2];
    const float* Wv = (const float*)d_in[3];
    const float* Wo = (const float*)d_in[4];
    float* out = (float*)d_out;

    float *gq, *gk, *gv, *ga;
    cudaGetSymbolAddress((void**)&gq, g_q);
    cudaGetSymbolAddress((void**)&gk, g_k);
    cudaGetSymbolAddress((void**)&gv, g_v);
    cudaGetSymbolAddress((void**)&ga, g_attn);

    cudaFuncSetAttribute(gemm_mma<0>, cudaFuncAttributeMaxDynamicSharedMemorySize, GEMM_SMEM);
    cudaFuncSetAttribute(gemm_mma<1>, cudaFuncAttributeMaxDynamicSharedMemorySize, GEMM_SMEM);

    dim3 gemm_grid(DM / 128, MM / 128);   // (8, 32)
    gemm_mma<1><<<gemm_grid, 256, GEMM_SMEM>>>(x, Wq, gq);
    gemm_mma<1><<<gemm_grid, 256, GEMM_SMEM>>>(x, Wk, gk);
    gemm_mma<1><<<gemm_grid, 256, GEMM_SMEM>>>(x, Wv, gv);

    flash_attn<<<dim3(TT / 64, NH, BB), 256>>>(gq, gk, gv, ga);

    gemm_mma<0><<<gemm_grid, 256, GEMM_SMEM>>>(ga, Wo, out);
}

// round 8
// speedup vs baseline: 2.6468x; 1.6405x over previous
#include <cuda_runtime.h>
#include <cuda_bf16.h>
#include <cuda_fp16.h>
#include <cstdint>

#define DM 1024
#define NH 16
#define HD 64
#define BB 2
#define TT 2048
#define MM (BB*TT)   // 4096 rows

// Scratch: Q, K, V in [B,H,T,D], attn out in [B,T,H*D]
__device__ float g_q[(size_t)MM * DM];
__device__ float g_k[(size_t)MM * DM];
__device__ float g_v[(size_t)MM * DM];
__device__ float g_attn[(size_t)MM * DM];

__device__ __forceinline__ uint32_t smem_addr_u32(const void* smem_ptr) {
    uint32_t addr;
    asm("{ .reg .u64 tmp; cvta.to.shared.u64 tmp, %1; cvt.u32.u64 %0, tmp; }"
        : "=r"(addr) : "l"(smem_ptr));
    return addr;
}

#define SMEM_SWIZZLE_128B(byte_offset) \
    ((byte_offset) ^ (((byte_offset) >> 3) & 0x70))

__device__ __forceinline__ void ldmatrix_x4(uint32_t& r0, uint32_t& r1,
                                            uint32_t& r2, uint32_t& r3,
                                            uint32_t addr) {
    asm volatile("ldmatrix.sync.aligned.m8n8.x4.shared.b16 {%0,%1,%2,%3}, [%4];"
                 : "=r"(r0), "=r"(r1), "=r"(r2), "=r"(r3) : "r"(addr));
}

__device__ __forceinline__ void ldmatrix_x4_trans(uint32_t& r0, uint32_t& r1,
                                                  uint32_t& r2, uint32_t& r3,
                                                  uint32_t addr) {
    asm volatile("ldmatrix.sync.aligned.m8n8.x4.trans.shared.b16 {%0,%1,%2,%3}, [%4];"
                 : "=r"(r0), "=r"(r1), "=r"(r2), "=r"(r3) : "r"(addr));
}

__device__ __forceinline__ void mma_bf16(float* d, const uint32_t* a,
                                         uint32_t b0, uint32_t b1) {
    asm volatile(
        "mma.sync.aligned.m16n8k16.row.col.f32.bf16.bf16.f32 "
        "{%0,%1,%2,%3}, {%4,%5,%6,%7}, {%8,%9}, {%0,%1,%2,%3};"
        : "+f"(d[0]), "+f"(d[1]), "+f"(d[2]), "+f"(d[3])
        : "r"(a[0]), "r"(a[1]), "r"(a[2]), "r"(a[3]), "r"(b0), "r"(b1));
}

__device__ __forceinline__ void mma_f16(float* d, const uint32_t* a,
                                        uint32_t b0, uint32_t b1) {
    asm volatile(
        "mma.sync.aligned.m16n8k16.row.col.f32.f16.f16.f32 "
        "{%0,%1,%2,%3}, {%4,%5,%6,%7}, {%8,%9}, {%0,%1,%2,%3};"
        : "+f"(d[0]), "+f"(d[1]), "+f"(d[2]), "+f"(d[3])
        : "r"(a[0]), "r"(a[1]), "r"(a[2]), "r"(a[3]), "r"(b0), "r"(b1));
}

__device__ __forceinline__ uint32_t pack_bf2(__nv_bfloat16 a, __nv_bfloat16 b) {
    return ((uint32_t)__bfloat16_as_ushort(b) << 16) | (uint32_t)__bfloat16_as_ushort(a);
}

__device__ __forceinline__ uint32_t pack_h2(float a, float b) {
    __half2 h = __floats2half2_rn(a, b);   // .x = a (low 16 bits)
    return *(uint32_t*)&h;
}

// fp32 -> bf16 hi/lo split (GEMM path)
__device__ __forceinline__ void split_store(char* phi, char* plo, uint32_t off,
                                            float4 v) {
    __nv_bfloat16 h0 = __float2bfloat16_rn(v.x);
    __nv_bfloat16 h1 = __float2bfloat16_rn(v.y);
    __nv_bfloat16 h2 = __float2bfloat16_rn(v.z);
    __nv_bfloat16 h3 = __float2bfloat16_rn(v.w);
    __nv_bfloat16 l0 = __float2bfloat16_rn(v.x - __bfloat162float(h0));
    __nv_bfloat16 l1 = __float2bfloat16_rn(v.y - __bfloat162float(h1));
    __nv_bfloat16 l2 = __float2bfloat16_rn(v.z - __bfloat162float(h2));
    __nv_bfloat16 l3 = __float2bfloat16_rn(v.w - __bfloat162float(h3));
    *(uint2*)(phi + off) = make_uint2(pack_bf2(h0, h1), pack_bf2(h2, h3));
    *(uint2*)(plo + off) = make_uint2(pack_bf2(l0, l1), pack_bf2(l2, l3));
}

// fp32 -> fp16 hi/lo split (flash path)
__device__ __forceinline__ void split_store_h(char* phi, char* plo, uint32_t off,
                                              float4 v) {
    __half h0 = __float2half_rn(v.x), h1 = __float2half_rn(v.y);
    __half h2 = __float2half_rn(v.z), h3 = __float2half_rn(v.w);
    float l0 = v.x - __half2float(h0), l1 = v.y - __half2float(h1);
    float l2 = v.z - __half2float(h2), l3 = v.w - __half2float(h3);
    __half2 hh0 = __halves2half2(h0, h1), hh1 = __halves2half2(h2, h3);
    *(uint2*)(phi + off) = make_uint2(*(uint32_t*)&hh0, *(uint32_t*)&hh1);
    *(uint2*)(plo + off) = make_uint2(pack_h2(l0, l1), pack_h2(l2, l3));
}

// exp2 on the FMA pipe (no MUFU). x clamped at -28; rel err ~2.4e-6.
__device__ __forceinline__ float fexp2(float x) {
    x = fmaxf(x, -28.f);
    float t = x + 12582912.f;          // round-to-nearest-int trick
    float i = t - 12582912.f;
    float f = x - i;                   // [-0.5, 0.5]
    float p = 0.0013333558f;
    p = fmaf(p, f, 0.0096181291f);
    p = fmaf(p, f, 0.0555041087f);
    p = fmaf(p, f, 0.2402265069f);
    p = fmaf(p, f, 0.6931471806f);
    p = fmaf(p, f, 1.0f);
    int ei = (int)i;
    return p * __int_as_float((127 + ei) << 23);
}

// ===========================================================================
// Warp-MMA GEMM (unchanged from R7): C = A @ B^T, bf16 hi/lo 3-MMA split.
// ===========================================================================
#define GEMM_SMEM 65536

template<int MODE>
__global__ __launch_bounds__(256, 2)
void gemm_mma(const float* __restrict__ A, const float* __restrict__ Bm,
              float* __restrict__ C)
{
    extern __shared__ __align__(1024) char smem[];
    char* sAh = smem;
    char* sAl = smem + 16384;
    char* sBh = smem + 32768;
    char* sBl = smem + 49152;
    const uint32_t uAh = smem_addr_u32(sAh);
    const uint32_t uAl = uAh + 16384;
    const uint32_t uBh = uAh + 32768;
    const uint32_t uBl = uAh + 49152;

    const int tid  = threadIdx.x;
    const int bcol = blockIdx.x;
    const int brow = blockIdx.y;
    const int warp = tid >> 5;
    const int lane = tid & 31;

    const int m0w = (warp >> 1) * 32;
    const int n0w = (warp & 1) * 64;

    const int ltile   = lane >> 3;
    const int within  = lane & 7;
    const int rowoff  = ((ltile & 1) << 3) + within;
    const int chalf   = (ltile >> 1) << 4;
    const int xorkey  = within << 4;

    const float* Ag = A  + (size_t)(brow * 128) * DM;
    const float* Bg = Bm + (size_t)(bcol * 128) * DM;

    float acc[2][8][4];
    #pragma unroll
    for (int i = 0; i < 2; i++)
        #pragma unroll
        for (int j = 0; j < 8; j++)
            #pragma unroll
            for (int q = 0; q < 4; q++) acc[i][j][q] = 0.f;

    for (int s = 0; s < 16; ++s) {
        #pragma unroll
        for (int it = 0; it < 8; ++it) {
            int idx = tid + it * 256;
            int r   = idx >> 4;
            int c4  = (idx & 15) << 2;
            float4 va = *(const float4*)(Ag + (size_t)r * DM + s * 64 + c4);
            float4 vb = *(const float4*)(Bg + (size_t)r * DM + s * 64 + c4);
            uint32_t off = SMEM_SWIZZLE_128B((uint32_t)(r * 128 + c4 * 2));
            split_store(sAh, sAl, off, va);
            split_store(sBh, sBl, off, vb);
        }
        __syncthreads();

        #pragma unroll
        for (int ks = 0; ks < 4; ++ks) {
            const uint32_t coff = (uint32_t)((ks * 32 + chalf) ^ xorkey);

            uint32_t ah[2][4], al[2][4];
            #pragma unroll
            for (int i = 0; i < 2; i++) {
                uint32_t ra = (uint32_t)((m0w + i * 16 + rowoff) * 128) + coff;
                ldmatrix_x4(ah[i][0], ah[i][1], ah[i][2], ah[i][3], uAh + ra);
                ldmatrix_x4(al[i][0], al[i][1], al[i][2], al[i][3], uAl + ra);
            }

            #pragma unroll
            for (int g = 0; g < 4; ++g) {
                uint32_t rb = (uint32_t)((n0w + g * 16 + rowoff) * 128) + coff;
                uint32_t bh[4], bl[4];
                ldmatrix_x4(bh[0], bh[1], bh[2], bh[3], uBh + rb);
                ldmatrix_x4(bl[0], bl[1], bl[2], bl[3], uBl + rb);
                #pragma unroll
                for (int jj = 0; jj < 2; ++jj) {
                    int j = g * 2 + jj;
                    #pragma unroll
                    for (int i = 0; i < 2; i++) {
                        mma_bf16(acc[i][j], ah[i], bh[jj], bh[2 + jj]);
                        mma_bf16(acc[i][j], ah[i], bl[jj], bl[2 + jj]);
                        mma_bf16(acc[i][j], al[i], bh[jj], bh[2 + jj]);
                    }
                }
            }
        }
        __syncthreads();
    }

    const int rfrag = lane >> 2;
    const int cfrag = (lane & 3) * 2;
    #pragma unroll
    for (int i = 0; i < 2; i++) {
        #pragma unroll
        for (int j = 0; j < 8; j++) {
            int m = brow * 128 + m0w + i * 16 + rfrag;
            int n = bcol * 128 + n0w + j * 8 + cfrag;
            float2 v0 = make_float2(acc[i][j][0], acc[i][j][1]);
            float2 v1 = make_float2(acc[i][j][2], acc[i][j][3]);
            if (MODE == 0) {
                *(float2*)(C + (size_t)m * DM + n)       = v0;
                *(float2*)(C + (size_t)(m + 8) * DM + n) = v1;
            } else {
                int h = n >> 6, d = n & 63;
                int b0 = m >> 11, t0 = m & 2047;
                *(float2*)(C + ((size_t)((b0 << 4) + h) * TT + t0) * HD + d) = v0;
                int m8 = m + 8;
                int b1 = m8 >> 11, t1 = m8 & 2047;
                *(float2*)(C + ((size_t)((b1 << 4) + h) * TT + t1) * HD + d) = v1;
            }
        }
    }
}

// ===========================================================================
// Tensor-core flash attention.  BR=128 q-rows/CTA, BC=64 kv-cols/iter.
// 8 warps, each owns 16 full rows -> softmax reduces over 4 lanes only.
// Q,K: fp16 hi/lo split (3 MMAs).  P,V: single fp16 (2 MMAs' worth -> 32).
// exp2 via FMA-pipe polynomial (zero MUFU).  Base-2 softmax (log2e folded
// into Q scale).
// ===========================================================================
#define FLASH_SMEM 57344   // Qh 16K | Ql 16K | Kh 8K | Kl 8K | Vh 8K

__global__ __launch_bounds__(256, 1)
void flash_mma(const float* __restrict__ gq, const float* __restrict__ gk,
               const float* __restrict__ gv, float* __restrict__ gout)
{
    extern __shared__ __align__(1024) char smem[];
    char* sQh = smem;
    char* sQl = smem + 16384;
    char* sKh = smem + 32768;
    char* sKl = smem + 40960;
    char* sVh = smem + 49152;
    const uint32_t uQh = smem_addr_u32(sQh);
    const uint32_t uQl = uQh + 16384;
    const uint32_t uKh = uQh + 32768;
    const uint32_t uKl = uQh + 40960;
    const uint32_t uVh = uQh + 49152;

    const int qb  = (int)gridDim.x - 1 - blockIdx.x;   // long CTAs first
    const int h   = blockIdx.y;
    const int b   = blockIdx.z;
    const int tid = threadIdx.x;
    const int warp = tid >> 5;
    const int lane = tid & 31;

    const int m0w = warp * 16;               // warp's 16 rows in the 128-row tile
    const int ltile  = lane >> 3;
    const int within = lane & 7;
    const int rowoff = ((ltile & 1) << 3) + within;
    const int chalf  = (ltile >> 1) << 4;
    const int xorkey = within << 4;
    const int g  = lane >> 2;                // accum row within m16
    const int t2 = lane & 3;                 // accum col pair index

    const size_t bh = (size_t)(b * NH + h) * TT;
    const float* qptr = gq + (bh + (size_t)qb * 128) * HD;
    const float QS = 0.125f * 1.4426950408889634f;   // (1/sqrt(64)) * log2(e)

    // ---- load Q (128x64), scale, fp16 hi/lo split into smem ----
    #pragma unroll
    for (int it = 0; it < 8; ++it) {
        int idx = tid + it * 256;            // float4 units, 0..2047
        int r   = idx >> 4;                  // 0..127
        int c4  = (idx & 15) << 2;
        float4 v = *(const float4*)(qptr + (size_t)r * HD + c4);
        v.x *= QS; v.y *= QS; v.z *= QS; v.w *= QS;
        uint32_t off = SMEM_SWIZZLE_128B((uint32_t)(r * 128 + c4 * 2));
        split_store_h(sQh, sQl, off, v);
    }
    __syncthreads();

    // ---- preload Q A-fragments (reused every KV block) ----
    uint32_t qh[4][4], ql[4][4];
    #pragma unroll
    for (int ks = 0; ks < 4; ++ks) {
        uint32_t coff = (uint32_t)((ks * 32 + chalf) ^ xorkey);
        uint32_t ra = (uint32_t)((m0w + rowoff) * 128) + coff;
        ldmatrix_x4(qh[ks][0], qh[ks][1], qh[ks][2], qh[ks][3], uQh + ra);
        ldmatrix_x4(ql[ks][0], ql[ks][1], ql[ks][2], ql[ks][3], uQl + ra);
    }

    float o[8][4];
    #pragma unroll
    for (int j = 0; j < 8; j++)
        #pragma unroll
        for (int q = 0; q < 4; q++) o[j][q] = 0.f;
    float m0 = -100000.f, m1 = -100000.f, l0 = 0.f, l1 = 0.f;

    const int r0g = qb * 128 + m0w + g;      // global row (accum slots 0,1)
    const int r1g = r0g + 8;                 // global row (accum slots 2,3)
    const int jb_max = 2 * qb + 1;

    for (int jb = 0; jb <= jb_max; ++jb) {
        const float* kptr = gk + (bh + (size_t)jb * 64) * HD;
        const float* vptr = gv + (bh + (size_t)jb * 64) * HD;
        __syncthreads();                     // prior iter done with K/V smem
        #pragma unroll
        for (int it = 0; it < 4; ++it) {
            int idx = tid + it * 256;        // 0..1023
            int r   = idx >> 4;              // 0..63
            int c4  = (idx & 15) << 2;
            uint32_t off = SMEM_SWIZZLE_128B((uint32_t)(r * 128 + c4 * 2));
            float4 kv = *(const float4*)(kptr + (size_t)r * HD + c4);
            split_store_h(sKh, sKl, off, kv);
            float4 vv = *(const float4*)(vptr + (size_t)r * HD + c4);
            *(uint2*)(sVh + off) = make_uint2(pack_h2(vv.x, vv.y),
                                              pack_h2(vv.z, vv.w));
        }
        __syncthreads();

        // ---- S = Q @ K^T (fp16 hi/lo, 3 MMAs per tile) ----
        float acc[8][4];
        #pragma unroll
        for (int j = 0; j < 8; j++)
            #pragma unroll
            for (int q = 0; q < 4; q++) acc[j][q] = 0.f;

        #pragma unroll
        for (int ks = 0; ks < 4; ++ks) {
            uint32_t coff = (uint32_t)((ks * 32 + chalf) ^ xorkey);
            #pragma unroll
            for (int g4 = 0; g4 < 4; ++g4) {
                uint32_t rb = (uint32_t)((g4 * 16 + rowoff) * 128) + coff;
                uint32_t kh[4], kl[4];
                ldmatrix_x4(kh[0], kh[1], kh[2], kh[3], uKh + rb);
                ldmatrix_x4(kl[0], kl[1], kl[2], kl[3], uKl + rb);
                #pragma unroll
                for (int jj = 0; jj < 2; ++jj) {
                    int j = g4 * 2 + jj;
                    mma_f16(acc[j], qh[ks], kh[jj], kh[2 + jj]);
                    mma_f16(acc[j], qh[ks], kl[jj], kl[2 + jj]);
                    mma_f16(acc[j], ql[ks], kh[jj], kh[2 + jj]);
                }
            }
        }

        // ---- causal mask (only the two diagonal-touching blocks) ----
        if (jb >= 2 * qb) {
            #pragma unroll
            for (int j = 0; j < 8; j++) {
                int cb = jb * 64 + j * 8 + t2 * 2;
                if (cb     > r0g) acc[j][0] = -30000.f;
                if (cb + 1 > r0g) acc[j][1] = -30000.f;
                if (cb     > r1g) acc[j][2] = -30000.f;
                if (cb + 1 > r1g) acc[j][3] = -30000.f;
            }
        }

        // ---- online softmax, base 2, FMA-pipe exp ----
        float mx0 = -30000.f, mx1 = -30000.f;
        #pragma unroll
        for (int j = 0; j < 8; j++) {
            mx0 = fmaxf(mx0, fmaxf(acc[j][0], acc[j][1]));
            mx1 = fmaxf(mx1, fmaxf(acc[j][2], acc[j][3]));
        }
        mx0 = fmaxf(mx0, __shfl_xor_sync(0xffffffffu, mx0, 1));
        mx0 = fmaxf(mx0, __shfl_xor_sync(0xffffffffu, mx0, 2));
        mx1 = fmaxf(mx1, __shfl_xor_sync(0xffffffffu, mx1, 1));
        mx1 = fmaxf(mx1, __shfl_xor_sync(0xffffffffu, mx1, 2));

        float mn0 = fmaxf(m0, mx0), mn1 = fmaxf(m1, mx1);
        float a0 = fexp2(m0 - mn0), a1 = fexp2(m1 - mn1);
        m0 = mn0; m1 = mn1;

        float rs0 = 0.f, rs1 = 0.f;
        #pragma unroll
        for (int j = 0; j < 8; j++) {
            acc[j][0] = fexp2(acc[j][0] - mn0);
            acc[j][1] = fexp2(acc[j][1] - mn0);
            acc[j][2] = fexp2(acc[j][2] - mn1);
            acc[j][3] = fexp2(acc[j][3] - mn1);
            rs0 += acc[j][0] + acc[j][1];
            rs1 += acc[j][2] + acc[j][3];
        }
        rs0 += __shfl_xor_sync(0xffffffffu, rs0, 1);
        rs0 += __shfl_xor_sync(0xffffffffu, rs0, 2);
        rs1 += __shfl_xor_sync(0xffffffffu, rs1, 1);
        rs1 += __shfl_xor_sync(0xffffffffu, rs1, 2);
        l0 = l0 * a0 + rs0;
        l1 = l1 * a1 + rs1;

        #pragma unroll
        for (int j = 0; j < 8; j++) {
            o[j][0] *= a0; o[j][1] *= a0;
            o[j][2] *= a1; o[j][3] *= a1;
        }

        // ---- pack P accum -> fp16 A fragments (register-only) ----
        uint32_t pf[4][4];
        #pragma unroll
        for (int j0 = 0; j0 < 4; ++j0) {
            pf[j0][0] = pack_h2(acc[2*j0][0],   acc[2*j0][1]);
            pf[j0][1] = pack_h2(acc[2*j0][2],   acc[2*j0][3]);
            pf[j0][2] = pack_h2(acc[2*j0+1][0], acc[2*j0+1][1]);
            pf[j0][3] = pack_h2(acc[2*j0+1][2], acc[2*j0+1][3]);
        }

        // ---- O += P @ V  (V via ldmatrix.trans as B operand) ----
        #pragma unroll
        for (int s0t = 0; s0t < 4; ++s0t) {
            #pragma unroll
            for (int d0t = 0; d0t < 4; ++d0t) {
                uint32_t addr = uVh + (uint32_t)((s0t * 16 + rowoff) * 128)
                              + (uint32_t)((d0t * 32 + chalf) ^ xorkey);
                uint32_t w0, w1, w2, w3;
                ldmatrix_x4_trans(w0, w1, w2, w3, addr);
                mma_f16(o[d0t * 2],     pf[s0t], w0, w1);
                mma_f16(o[d0t * 2 + 1], pf[s0t], w2, w3);
            }
        }
    }

    // ---- epilogue: O /= l, write [B,T,H*D] ----
    float inv0 = 1.f / l0, inv1 = 1.f / l1;
    const int tg0 = qb * 128 + m0w + g;
    const int tg1 = tg0 + 8;
    #pragma unroll
    for (int j = 0; j < 8; j++) {
        int d = h * HD + j * 8 + t2 * 2;
        *(float2*)(gout + (size_t)(b * TT + tg0) * DM + d) =
            make_float2(o[j][0] * inv0, o[j][1] * inv0);
        *(float2*)(gout + (size_t)(b * TT + tg1) * DM + d) =
            make_float2(o[j][2] * inv1, o[j][3] * inv1);
    }
}

// ---------------------------------------------------------------------------
extern "C" void kernel_launch(void* const* d_in, const int* in_sizes, int n_in,
                              void* d_out, int out_size)
{
    const float* x  = (const float*)d_in[0];
    const float* Wq = (const float*)d_in[1];
    const float* Wk = (const float*)d_in[2];
    const float* Wv = (const float*)d_in[3];
    const float* Wo = (const float*)d_in[4];
    float* out = (float*)d_out;

    float *gq, *gk, *gv, *ga;
    cudaGetSymbolAddress((void**)&gq, g_q);
    cudaGetSymbolAddress((void**)&gk, g_k);
    cudaGetSymbolAddress((void**)&gv, g_v);
    cudaGetSymbolAddress((void**)&ga, g_attn);

    cudaFuncSetAttribute(gemm_mma<0>, cudaFuncAttributeMaxDynamicSharedMemorySize, GEMM_SMEM);
    cudaFuncSetAttribute(gemm_mma<1>, cudaFuncAttributeMaxDynamicSharedMemorySize, GEMM_SMEM);
    cudaFuncSetAttribute(flash_mma,   cudaFuncAttributeMaxDynamicSharedMemorySize, FLASH_SMEM);

    dim3 gemm_grid(DM / 128, MM / 128);   // (8, 32)
    gemm_mma<1><<<gemm_grid, 256, GEMM_SMEM>>>(x, Wq, gq);
    gemm_mma<1><<<gemm_grid, 256, GEMM_SMEM>>>(x, Wk, gk);
    gemm_mma<1><<<gemm_grid, 256, GEMM_SMEM>>>(x, Wv, gv);

    flash_mma<<<dim3(TT / 128, NH, BB), 256, FLASH_SMEM>>>(gq, gk, gv, ga);

    gemm_mma<0><<<gemm_grid, 256, GEMM_SMEM>>>(ga, Wo, out);
}